// round 5
// baseline (speedup 1.0000x reference)
#include <cuda_runtime.h>

#define NN  100000
#define EE  3200000
#define GMAX 128

// ---------------- scratch (no allocations allowed) ----------------
// 16B alignment required for float4 loads / red.v4 stores.
__device__ __align__(16) float d_h  [NN * 64];   // x @ W1
__device__ __align__(16) float d_h1 [NN * 64];   // gcn1 output, also "x2"
__device__ __align__(16) float d_h2 [NN * 64];   // z @ W2 (pre-aggregation)
__device__ __align__(16) float d_agg[NN * 64];   // edge aggregation buffer (reused)
__device__ float d_deg [NN];
__device__ float d_dinv[NN];
__device__ int   d_root[GMAX];
__device__ __align__(16) float d_rc  [GMAX * 64]; // per-graph: relu(x[root]) @ W2[64:192]
__device__ __align__(16) float d_sums[GMAX * 64];
__device__ int   d_cnt [GMAX];

// ---------------- kernels ----------------

__global__ void k_init(int n, int g) {
    int i = blockIdx.x * blockDim.x + threadIdx.x;
    int tot = n * 64;
    if (i < tot) d_agg[i] = 0.0f;
    if (i < n)   d_deg[i] = 0.0f;
    if (i < g * 64) d_sums[i] = 0.0f;
    if (i < g) { d_cnt[i] = 0; d_root[i] = n - 1; }
}

__global__ void k_zero_agg(int n) {
    int i = blockIdx.x * blockDim.x + threadIdx.x;
    if (i < n * 64) d_agg[i] = 0.0f;
}

// h = x @ W1   (one node per block, 64 threads = 64 output features)
__global__ void k_gemm1(const float* __restrict__ x, const float* __restrict__ W1) {
    int i = blockIdx.x;
    int j = threadIdx.x;
    __shared__ float xs[128];
    xs[j]      = x[(size_t)i * 128 + j];
    xs[64 + j] = x[(size_t)i * 128 + 64 + j];
    __syncthreads();
    float acc = 0.0f;
#pragma unroll 8
    for (int k = 0; k < 128; k++)
        acc = fmaf(xs[k], __ldg(&W1[k * 64 + j]), acc);
    d_h[(size_t)i * 64 + j] = acc;
}

__global__ void k_deg(const int* __restrict__ dst, int e) {
    int i = blockIdx.x * blockDim.x + threadIdx.x;
    if (i < e) atomicAdd(&d_deg[dst[i]], 1.0f);
}

__global__ void k_dinv(int n) {
    int i = blockIdx.x * blockDim.x + threadIdx.x;
    if (i < n) d_dinv[i] = rsqrtf(d_deg[i] + 1.0f);
}

// edge scatter: agg[dst] += h[src] * dinv[src]*dinv[dst]
// 16 lanes per edge, float4 loads + red.global.add.v4.f32
__global__ void k_scatter(const int* __restrict__ src,
                          const int* __restrict__ dst,
                          int e, int which) {
    unsigned int idx = blockIdx.x * blockDim.x + threadIdx.x;
    int ei = idx >> 4;
    int q  = idx & 15;
    if (ei >= e) return;
    const float* h = which ? d_h2 : d_h;
    int s = src[ei];
    int d = dst[ei];
    float nrm = d_dinv[s] * d_dinv[d];
    float4 v = *reinterpret_cast<const float4*>(h + (size_t)s * 64 + q * 4);
    v.x *= nrm; v.y *= nrm; v.z *= nrm; v.w *= nrm;
    float* p = d_agg + (size_t)d * 64 + q * 4;
    asm volatile("red.global.add.v4.f32 [%0], {%1,%2,%3,%4};"
                 :: "l"(p), "f"(v.x), "f"(v.y), "f"(v.z), "f"(v.w) : "memory");
}

// h1 = agg + h * dinv^2 + b1
__global__ void k_finish1(const float* __restrict__ b1, int n) {
    int idx = blockIdx.x * blockDim.x + threadIdx.x;
    if (idx >= n * 64) return;
    int i = idx >> 6, j = idx & 63;
    float di = d_dinv[i];
    d_h1[idx] = d_agg[idx] + d_h[idx] * di * di + b1[j];
}

// root index (first node of each sorted batch segment) + counts
__global__ void k_root(const int* __restrict__ batch, int n) {
    int i = blockIdx.x * blockDim.x + threadIdx.x;
    if (i >= n) return;
    int g = batch[i];
    atomicMin(&d_root[g], i);
    atomicAdd(&d_cnt[g], 1);
}

// rc[g] = relu(x[root_g]) @ W2[64:192]   (one graph per block)
__global__ void k_rc(const float* __restrict__ x, const float* __restrict__ W2) {
    int g = blockIdx.x;
    int j = threadIdx.x;
    int r = d_root[g];
    __shared__ float xs[128];
    xs[j]      = fmaxf(x[(size_t)r * 128 + j], 0.0f);
    xs[64 + j] = fmaxf(x[(size_t)r * 128 + 64 + j], 0.0f);
    __syncthreads();
    float acc = 0.0f;
#pragma unroll 8
    for (int k = 0; k < 128; k++)
        acc = fmaf(xs[k], __ldg(&W2[(64 + k) * 64 + j]), acc);
    d_rc[g * 64 + j] = acc;
}

// h2 = relu(h1) @ W2[0:64] + rc[batch]
__global__ void k_gemm2(const float* __restrict__ W2,
                        const int* __restrict__ batch) {
    int i = blockIdx.x;
    int j = threadIdx.x;
    __shared__ float zs[64];
    zs[j] = fmaxf(d_h1[(size_t)i * 64 + j], 0.0f);
    __syncthreads();
    int g = batch[i];
    float acc = d_rc[g * 64 + j];
#pragma unroll 8
    for (int k = 0; k < 64; k++)
        acc = fmaf(zs[k], __ldg(&W2[k * 64 + j]), acc);
    d_h2[(size_t)i * 64 + j] = acc;
}

// per-node: relu(agg + h2*dinv^2 + b2) -> atomic sum per graph (first 64 feats)
__global__ void k_final(const float* __restrict__ b2,
                        const int* __restrict__ batch) {
    int i = blockIdx.x;
    int j = threadIdx.x;
    float di = d_dinv[i];
    int g = batch[i];
    size_t idx = (size_t)i * 64 + j;
    float v = fmaxf(d_agg[idx] + d_h2[idx] * di * di + b2[j], 0.0f);
    atomicAdd(&d_sums[g * 64 + j], v);
}

// out[g][0:64] = sums/max(cnt,1);  out[g][64:128] = h1[root_g] (or 0 if empty)
__global__ void k_out(float* __restrict__ out) {
    int g = blockIdx.x;
    int j = threadIdx.x;
    float c = (float)d_cnt[g];
    float val;
    if (j < 64) {
        val = d_sums[g * 64 + j] / fmaxf(c, 1.0f);
    } else {
        val = (c > 0.0f) ? d_h1[(size_t)d_root[g] * 64 + (j - 64)] : 0.0f;
    }
    out[g * 128 + j] = val;
}

// ---------------- launcher ----------------
extern "C" void kernel_launch(void* const* d_in, const int* in_sizes, int n_in,
                              void* d_out, int out_size) {
    const float* x     = (const float*)d_in[0];
    const int*   ei    = (const int*)d_in[1];    // int32! (JAX x64 disabled)
    const int*   batch = (const int*)d_in[2];    // int32!
    const float* W1    = (const float*)d_in[3];
    const float* b1    = (const float*)d_in[4];
    const float* W2    = (const float*)d_in[5];
    const float* b2    = (const float*)d_in[6];
    float*       out   = (float*)d_out;

    int n = in_sizes[0] / 128;   // 100000
    int e = in_sizes[1] / 2;     // 3200000
    int g = out_size / 128;      // 128

    const int* src = ei;
    const int* dst = ei + e;

    int nb_nf  = (n * 64 + 255) / 256;
    int nb_e   = (e + 255) / 256;
    int nb_n   = (n + 255) / 256;
    int nb_sc  = (int)(((long long)e * 16 + 255) / 256);

    k_init    <<<nb_nf, 256>>>(n, g);
    k_gemm1   <<<n, 64>>>(x, W1);
    k_deg     <<<nb_e, 256>>>(dst, e);
    k_dinv    <<<nb_n, 256>>>(n);
    k_scatter <<<nb_sc, 256>>>(src, dst, e, 0);
    k_finish1 <<<nb_nf, 256>>>(b1, n);
    k_root    <<<nb_n, 256>>>(batch, n);
    k_rc      <<<g, 64>>>(x, W2);
    k_gemm2   <<<n, 64>>>(W2, batch);
    k_zero_agg<<<nb_nf, 256>>>(n);
    k_scatter <<<nb_sc, 256>>>(src, dst, e, 1);
    k_final   <<<n, 64>>>(b2, batch);
    k_out     <<<g, 128>>>(out);
}

// round 6
// speedup vs baseline: 1.6698x; 1.6698x over previous
#include <cuda_runtime.h>

#define NN  100000
#define EE  3200000
#define GMAX 128

// ---------------- scratch (no allocations allowed) ----------------
__device__ __align__(16) float d_h  [NN * 64];   // x @ W1
__device__ __align__(16) float d_h1 [NN * 64];   // gcn1 output (pre-relu)
__device__ __align__(16) float d_h2 [NN * 64];   // z @ W2 (pre-aggregation)
__device__ float d_dinv[NN];
__device__ int   d_ideg [NN];     // in-degree (edges by dst)
__device__ int   d_start[NN];     // CSR row starts (by dst)
__device__ int   d_cur  [NN];     // placement cursors
__device__ int   d_esrc [EE];     // src ids sorted by dst
__device__ int   d_bsum [256];
__device__ int   d_boff [256];
__device__ int   d_root [GMAX];
__device__ __align__(16) float d_rc    [GMAX * 64]; // relu(x[root]) @ W2[64:192]
__device__ __align__(16) float d_rooth1[GMAX * 64]; // h1 at roots
__device__ __align__(16) float d_sums  [GMAX * 64];
__device__ int   d_cnt [GMAX];

// ---------------- setup kernels ----------------

__global__ void k_init(int n, int g) {
    int i = blockIdx.x * blockDim.x + threadIdx.x;
    if (i < n) d_ideg[i] = 0;
    if (i < g * 64) d_sums[i] = 0.0f;
    if (i < g) { d_cnt[i] = 0; d_root[i] = n - 1; }
}

__global__ void k_hist(const int* __restrict__ dst, int e) {
    int i = blockIdx.x * blockDim.x + threadIdx.x;
    if (i < e) atomicAdd(&d_ideg[dst[i]], 1);
}

// block scan: 1024 elems / block (256 thr x 4)
__global__ void k_scan1(int n) {
    __shared__ int sm[256];
    int t = threadIdx.x, b = blockIdx.x;
    int base = b * 1024 + t * 4;
    int v[4]; int s = 0;
#pragma unroll
    for (int u = 0; u < 4; u++) {
        int i = base + u;
        v[u] = (i < n) ? d_ideg[i] : 0;
        s += v[u];
    }
    sm[t] = s; __syncthreads();
#pragma unroll
    for (int off = 1; off < 256; off <<= 1) {
        int x = (t >= off) ? sm[t - off] : 0;
        __syncthreads();
        sm[t] += x;
        __syncthreads();
    }
    int excl = sm[t] - s;
#pragma unroll
    for (int u = 0; u < 4; u++) {
        int i = base + u;
        if (i < n) d_start[i] = excl;
        excl += v[u];
    }
    if (t == 255) d_bsum[b] = sm[255];
}

__global__ void k_scan2(int nb) {
    __shared__ int sm[128];
    int t = threadIdx.x;
    int v = (t < nb) ? d_bsum[t] : 0;
    sm[t] = v; __syncthreads();
#pragma unroll
    for (int off = 1; off < 128; off <<= 1) {
        int x = (t >= off) ? sm[t - off] : 0;
        __syncthreads();
        sm[t] += x;
        __syncthreads();
    }
    d_boff[t] = sm[t] - v;
}

// add-back + cursors + dinv
__global__ void k_scan3(int n) {
    int i = blockIdx.x * blockDim.x + threadIdx.x;
    if (i >= n) return;
    int st = d_start[i] + d_boff[i >> 10];
    d_start[i] = st;
    d_cur[i] = st;
    d_dinv[i] = rsqrtf((float)d_ideg[i] + 1.0f);
}

__global__ void k_place(const int* __restrict__ src, const int* __restrict__ dst, int e) {
    int i = blockIdx.x * blockDim.x + threadIdx.x;
    if (i >= e) return;
    int d = dst[i];
    int pos = atomicAdd(&d_cur[d], 1);
    d_esrc[pos] = src[i];
}

// root index (first node of each sorted batch segment) + counts
__global__ void k_root(const int* __restrict__ batch, int n) {
    int i = blockIdx.x * blockDim.x + threadIdx.x;
    if (i >= n) return;
    int g = batch[i];
    atomicMin(&d_root[g], i);
    atomicAdd(&d_cnt[g], 1);
}

// ---------------- dense math ----------------

// h = x @ W1   (one node per block, 64 threads)
__global__ void k_gemm1(const float* __restrict__ x, const float* __restrict__ W1) {
    int i = blockIdx.x;
    int j = threadIdx.x;
    __shared__ float xs[128];
    xs[j]      = x[(size_t)i * 128 + j];
    xs[64 + j] = x[(size_t)i * 128 + 64 + j];
    __syncthreads();
    float acc = 0.0f;
#pragma unroll 8
    for (int k = 0; k < 128; k++)
        acc = fmaf(xs[k], __ldg(&W1[k * 64 + j]), acc);
    d_h[(size_t)i * 64 + j] = acc;
}

// rc[g] = relu(x[root_g]) @ W2[64:192]
__global__ void k_rc(const float* __restrict__ x, const float* __restrict__ W2) {
    int g = blockIdx.x;
    int j = threadIdx.x;
    int r = d_root[g];
    __shared__ float xs[128];
    xs[j]      = fmaxf(x[(size_t)r * 128 + j], 0.0f);
    xs[64 + j] = fmaxf(x[(size_t)r * 128 + 64 + j], 0.0f);
    __syncthreads();
    float acc = 0.0f;
#pragma unroll 8
    for (int k = 0; k < 128; k++)
        acc = fmaf(xs[k], __ldg(&W2[(64 + k) * 64 + j]), acc);
    d_rc[g * 64 + j] = acc;
}

// h2 = relu(h1) @ W2[0:64] + rc[batch]
__global__ void k_gemm2(const float* __restrict__ W2, const int* __restrict__ batch) {
    int i = blockIdx.x;
    int j = threadIdx.x;
    __shared__ float zs[64];
    zs[j] = fmaxf(d_h1[(size_t)i * 64 + j], 0.0f);
    __syncthreads();
    int g = batch[i];
    float acc = d_rc[g * 64 + j];
#pragma unroll 8
    for (int k = 0; k < 64; k++)
        acc = fmaf(zs[k], __ldg(&W2[k * 64 + j]), acc);
    d_h2[(size_t)i * 64 + j] = acc;
}

// ---------------- gather aggregation (no atomics) ----------------

// h1[i] = sum_{e in CSR(i)} h[src_e]*dinv[src]*dinv[i] + h[i]*dinv[i]^2 + b1
__global__ void k_gather1(const float* __restrict__ b1, const int* __restrict__ batch, int n) {
    int node = (blockIdx.x * blockDim.x + threadIdx.x) >> 4;
    int q = threadIdx.x & 15;
    if (node >= n) return;
    float di = d_dinv[node];
    int s0 = d_start[node];
    int e1 = s0 + d_ideg[node];
    float4 acc = make_float4(0.f, 0.f, 0.f, 0.f);
#pragma unroll 4
    for (int e = s0; e < e1; e++) {
        int s = __ldg(&d_esrc[e]);
        float nr = __ldg(&d_dinv[s]) * di;
        float4 v = *reinterpret_cast<const float4*>(d_h + (size_t)s * 64 + (q << 2));
        acc.x = fmaf(v.x, nr, acc.x); acc.y = fmaf(v.y, nr, acc.y);
        acc.z = fmaf(v.z, nr, acc.z); acc.w = fmaf(v.w, nr, acc.w);
    }
    float dd = di * di;
    float4 hv = *reinterpret_cast<const float4*>(d_h + (size_t)node * 64 + (q << 2));
    float4 bb = *reinterpret_cast<const float4*>(b1 + (q << 2));
    float4 r;
    r.x = acc.x + hv.x * dd + bb.x;
    r.y = acc.y + hv.y * dd + bb.y;
    r.z = acc.z + hv.z * dd + bb.z;
    r.w = acc.w + hv.w * dd + bb.w;
    *reinterpret_cast<float4*>(d_h1 + (size_t)node * 64 + (q << 2)) = r;
    int g = batch[node];
    if (d_root[g] == node)
        *reinterpret_cast<float4*>(d_rooth1 + g * 64 + (q << 2)) = r;
}

// per node: v = relu(gather(h2) + h2[i]*dinv^2 + b2), block-reduced sum into d_sums
__global__ void k_gather2(const float* __restrict__ b2, const int* __restrict__ batch, int n) {
    int node = (blockIdx.x * 256 + threadIdx.x) >> 4;
    int q = threadIdx.x & 15;
    bool valid = node < n;
    int nd = valid ? node : (n - 1);
    float di = d_dinv[nd];
    int s0 = d_start[nd];
    int e1 = s0 + (valid ? d_ideg[nd] : 0);
    float4 acc = make_float4(0.f, 0.f, 0.f, 0.f);
#pragma unroll 4
    for (int e = s0; e < e1; e++) {
        int s = __ldg(&d_esrc[e]);
        float nr = __ldg(&d_dinv[s]) * di;
        float4 v = *reinterpret_cast<const float4*>(d_h2 + (size_t)s * 64 + (q << 2));
        acc.x = fmaf(v.x, nr, acc.x); acc.y = fmaf(v.y, nr, acc.y);
        acc.z = fmaf(v.z, nr, acc.z); acc.w = fmaf(v.w, nr, acc.w);
    }
    int g = batch[nd];
    float4 v = make_float4(0.f, 0.f, 0.f, 0.f);
    if (valid) {
        float dd = di * di;
        float4 hv = *reinterpret_cast<const float4*>(d_h2 + (size_t)nd * 64 + (q << 2));
        float4 bb = *reinterpret_cast<const float4*>(b2 + (q << 2));
        v.x = fmaxf(acc.x + hv.x * dd + bb.x, 0.f);
        v.y = fmaxf(acc.y + hv.y * dd + bb.y, 0.f);
        v.z = fmaxf(acc.z + hv.z * dd + bb.z, 0.f);
        v.w = fmaxf(acc.w + hv.w * dd + bb.w, 0.f);
    }
    __shared__ float4 sv[256];
    __shared__ int sg[16];
    int grp = threadIdx.x >> 4;
    if (q == 0) sg[grp] = g;
    sv[threadIdx.x] = v;
    __syncthreads();
    int uni = __syncthreads_and(g == sg[0]);
    if (uni) {
#pragma unroll
        for (int st = 8; st >= 1; st >>= 1) {
            if (grp < st) {
                float4 o = sv[threadIdx.x + (st << 4)];
                sv[threadIdx.x].x += o.x; sv[threadIdx.x].y += o.y;
                sv[threadIdx.x].z += o.z; sv[threadIdx.x].w += o.w;
            }
            __syncthreads();
        }
        if (grp == 0) {
            float4 r = sv[q];
            float* p = d_sums + sg[0] * 64 + (q << 2);
            asm volatile("red.global.add.v4.f32 [%0], {%1,%2,%3,%4};"
                         :: "l"(p), "f"(r.x), "f"(r.y), "f"(r.z), "f"(r.w) : "memory");
        }
    } else {
        float* p = d_sums + g * 64 + (q << 2);
        asm volatile("red.global.add.v4.f32 [%0], {%1,%2,%3,%4};"
                     :: "l"(p), "f"(v.x), "f"(v.y), "f"(v.z), "f"(v.w) : "memory");
    }
}

// out[g][0:64] = sums/max(cnt,1);  out[g][64:128] = h1[root_g] (0 if empty)
__global__ void k_out(float* __restrict__ out) {
    int g = blockIdx.x;
    int j = threadIdx.x;
    float c = (float)d_cnt[g];
    float val;
    if (j < 64) val = d_sums[g * 64 + j] / fmaxf(c, 1.0f);
    else        val = (c > 0.0f) ? d_rooth1[g * 64 + (j - 64)] : 0.0f;
    out[g * 128 + j] = val;
}

// ---------------- launcher ----------------
extern "C" void kernel_launch(void* const* d_in, const int* in_sizes, int n_in,
                              void* d_out, int out_size) {
    const float* x     = (const float*)d_in[0];
    const int*   ei    = (const int*)d_in[1];    // int32 (JAX x64 disabled)
    const int*   batch = (const int*)d_in[2];
    const float* W1    = (const float*)d_in[3];
    const float* b1    = (const float*)d_in[4];
    const float* W2    = (const float*)d_in[5];
    const float* b2    = (const float*)d_in[6];
    float*       out   = (float*)d_out;

    int n = in_sizes[0] / 128;   // 100000
    int e = in_sizes[1] / 2;     // 3200000
    int g = out_size / 128;      // 128

    const int* src = ei;
    const int* dst = ei + e;

    int nb_n    = (n + 255) / 256;
    int nb_e    = (e + 255) / 256;
    int nb_scan = (n + 1023) / 1024;
    int nb_gth  = (n * 16 + 255) / 256;

    k_init    <<<nb_n, 256>>>(n, g);
    k_hist    <<<nb_e, 256>>>(dst, e);
    k_scan1   <<<nb_scan, 256>>>(n);
    k_scan2   <<<1, 128>>>(nb_scan);
    k_scan3   <<<nb_n, 256>>>(n);
    k_place   <<<nb_e, 256>>>(src, dst, e);
    k_gemm1   <<<n, 64>>>(x, W1);
    k_root    <<<nb_n, 256>>>(batch, n);
    k_rc      <<<g, 64>>>(x, W2);
    k_gather1 <<<nb_gth, 256>>>(b1, batch, n);
    k_gemm2   <<<n, 64>>>(W2, batch);
    k_gather2 <<<nb_gth, 256>>>(b2, batch, n);
    k_out     <<<g, 128>>>(out);
}

// round 8
// speedup vs baseline: 1.9625x; 1.1753x over previous
#include <cuda_runtime.h>

#define NN  100000
#define EE  3200000
#define GMAX 128

// ---------------- scratch (no allocations allowed) ----------------
__device__ __align__(16) float d_h  [NN * 64];   // x @ W1
__device__ __align__(16) float d_h2 [NN * 64];   // layer-2 pre-aggregation
__device__ float d_dinv[NN];
__device__ int   d_ideg [NN];     // in-degree (edges by dst)
__device__ int   d_start[NN];     // CSR row starts (by dst)
__device__ int   d_cur  [NN];     // placement cursors
__device__ int   d_esrc [EE];     // src ids sorted by dst
__device__ int   d_bsum [256];
__device__ int   d_boff [256];
__device__ int   d_root [GMAX];
__device__ __align__(16) float d_rc    [GMAX * 64]; // relu(x[root]) @ W2[64:192]
__device__ __align__(16) float d_rooth1[GMAX * 64]; // h1 at roots
__device__ __align__(16) float d_sums  [GMAX * 64];
__device__ int   d_cnt [GMAX];

// ---------------- setup kernels ----------------

__global__ void k_init(int n, int g) {
    int i = blockIdx.x * blockDim.x + threadIdx.x;
    if (i < n) d_ideg[i] = 0;
    if (i < g * 64) d_sums[i] = 0.0f;
    if (i < g) { d_cnt[i] = 0; d_root[i] = n - 1; }
}

__global__ void k_hist(const int* __restrict__ dst, int e) {
    int i = blockIdx.x * blockDim.x + threadIdx.x;
    if (i < e) atomicAdd(&d_ideg[dst[i]], 1);
}

// block scan: 1024 elems / block (256 thr x 4)
__global__ void k_scan1(int n) {
    __shared__ int sm[256];
    int t = threadIdx.x, b = blockIdx.x;
    int base = b * 1024 + t * 4;
    int v[4]; int s = 0;
#pragma unroll
    for (int u = 0; u < 4; u++) {
        int i = base + u;
        v[u] = (i < n) ? d_ideg[i] : 0;
        s += v[u];
    }
    sm[t] = s; __syncthreads();
#pragma unroll
    for (int off = 1; off < 256; off <<= 1) {
        int x = (t >= off) ? sm[t - off] : 0;
        __syncthreads();
        sm[t] += x;
        __syncthreads();
    }
    int excl = sm[t] - s;
#pragma unroll
    for (int u = 0; u < 4; u++) {
        int i = base + u;
        if (i < n) d_start[i] = excl;
        excl += v[u];
    }
    if (t == 255) d_bsum[b] = sm[255];
}

__global__ void k_scan2(int nb) {
    __shared__ int sm[128];
    int t = threadIdx.x;
    int v = (t < nb) ? d_bsum[t] : 0;
    sm[t] = v; __syncthreads();
#pragma unroll
    for (int off = 1; off < 128; off <<= 1) {
        int x = (t >= off) ? sm[t - off] : 0;
        __syncthreads();
        sm[t] += x;
        __syncthreads();
    }
    d_boff[t] = sm[t] - v;
}

// add-back + cursors + dinv
__global__ void k_scan3(int n) {
    int i = blockIdx.x * blockDim.x + threadIdx.x;
    if (i >= n) return;
    int st = d_start[i] + d_boff[i >> 10];
    d_start[i] = st;
    d_cur[i] = st;
    d_dinv[i] = rsqrtf((float)d_ideg[i] + 1.0f);
}

// ---------------- fused setup: place | gemm1 | root (block-partitioned) ----------
// blocks [0, nbE)              : CSR placement
// blocks [nbE, nbE+nbG)        : h = x @ W1  (16 lanes/node, 4 outs/lane)
// blocks [nbE+nbG, nbE+nbG+nbN): root/cnt scan
__global__ void k_setup(const int* __restrict__ src, const int* __restrict__ dst,
                        const float* __restrict__ x, const float* __restrict__ W1,
                        const int* __restrict__ batch,
                        int e, int n, int nbE, int nbG) {
    int role_b = blockIdx.x;
    if (role_b < nbE) {
        int i = role_b * 256 + threadIdx.x;
        if (i < e) {
            int d = dst[i];
            int pos = atomicAdd(&d_cur[d], 1);
            d_esrc[pos] = src[i];
        }
        return;
    }
    role_b -= nbE;
    if (role_b < nbG) {
        int node = (role_b * 256 + threadIdx.x) >> 4;
        int q  = threadIdx.x & 15;
        int nl = threadIdx.x >> 4;
        __shared__ float4 xs[16][32];
        bool valid = node < n;
        int nd = valid ? node : (n - 1);
        const float4* xr = reinterpret_cast<const float4*>(x + (size_t)nd * 128);
        xs[nl][q]      = xr[q];
        xs[nl][16 + q] = xr[16 + q];
        __syncwarp();
        const float4* W = reinterpret_cast<const float4*>(W1);
        const float* xf = reinterpret_cast<const float*>(xs[nl]);
        float4 acc = make_float4(0.f, 0.f, 0.f, 0.f);
#pragma unroll 8
        for (int k = 0; k < 128; k++) {
            float xv = xf[k];
            float4 w = __ldg(&W[k * 16 + q]);
            acc.x = fmaf(xv, w.x, acc.x);
            acc.y = fmaf(xv, w.y, acc.y);
            acc.z = fmaf(xv, w.z, acc.z);
            acc.w = fmaf(xv, w.w, acc.w);
        }
        if (valid)
            *reinterpret_cast<float4*>(d_h + (size_t)node * 64 + (q << 2)) = acc;
        return;
    }
    role_b -= nbG;
    int i = role_b * 256 + threadIdx.x;
    if (i < n) {
        int g = batch[i];
        atomicMin(&d_root[g], i);
        atomicAdd(&d_cnt[g], 1);
    }
}

// rc[g] = relu(x[root_g]) @ W2[64:192]
__global__ void k_rc(const float* __restrict__ x, const float* __restrict__ W2) {
    int g = blockIdx.x;
    int j = threadIdx.x;
    int r = d_root[g];
    __shared__ float xs[128];
    xs[j]      = fmaxf(x[(size_t)r * 128 + j], 0.0f);
    xs[64 + j] = fmaxf(x[(size_t)r * 128 + 64 + j], 0.0f);
    __syncthreads();
    float acc = 0.0f;
#pragma unroll 8
    for (int k = 0; k < 128; k++)
        acc = fmaf(xs[k], __ldg(&W2[(64 + k) * 64 + j]), acc);
    d_rc[g * 64 + j] = acc;
}

// ---------------- fused gather1 + gemm2 ----------------
// h1 = gather(h) + h*dinv^2 + b1        (h1 only stored for roots)
// h2 = relu(h1) @ W2[0:64] + rc[batch]  (computed in-block via smem)
__global__ void k_gather1(const float* __restrict__ b1, const int* __restrict__ batch,
                          const float* __restrict__ W2, int n) {
    int node = (blockIdx.x * 256 + threadIdx.x) >> 4;
    int q  = threadIdx.x & 15;
    int nl = threadIdx.x >> 4;
    __shared__ float4 zs[16][16];
    bool valid = node < n;
    int nd = valid ? node : (n - 1);
    float di = d_dinv[nd];
    int s0 = d_start[nd];
    int e1 = s0 + (valid ? d_ideg[nd] : 0);
    float4 acc = make_float4(0.f, 0.f, 0.f, 0.f);
#pragma unroll 4
    for (int e = s0; e < e1; e++) {
        int s = __ldg(&d_esrc[e]);
        float nr = __ldg(&d_dinv[s]) * di;
        float4 v = *reinterpret_cast<const float4*>(d_h + (size_t)s * 64 + (q << 2));
        acc.x = fmaf(v.x, nr, acc.x); acc.y = fmaf(v.y, nr, acc.y);
        acc.z = fmaf(v.z, nr, acc.z); acc.w = fmaf(v.w, nr, acc.w);
    }
    float dd = di * di;
    float4 hv = *reinterpret_cast<const float4*>(d_h + (size_t)nd * 64 + (q << 2));
    float4 bb = *reinterpret_cast<const float4*>(b1 + (q << 2));
    float4 r;
    r.x = acc.x + hv.x * dd + bb.x;
    r.y = acc.y + hv.y * dd + bb.y;
    r.z = acc.z + hv.z * dd + bb.z;
    r.w = acc.w + hv.w * dd + bb.w;

    int g = batch[nd];
    if (valid && d_root[g] == node)
        *reinterpret_cast<float4*>(d_rooth1 + g * 64 + (q << 2)) = r;

    // z = relu(h1), staged to smem for the in-block GEMM
    float4 z;
    z.x = fmaxf(r.x, 0.f); z.y = fmaxf(r.y, 0.f);
    z.z = fmaxf(r.z, 0.f); z.w = fmaxf(r.w, 0.f);
    zs[nl][q] = z;
    __syncwarp();

    const float4* W = reinterpret_cast<const float4*>(W2);
    float4 a2 = *reinterpret_cast<const float4*>(d_rc + g * 64 + (q << 2));
    const float* zf = reinterpret_cast<const float*>(zs[nl]);
#pragma unroll 8
    for (int k = 0; k < 64; k++) {
        float zv = zf[k];
        float4 w = __ldg(&W[k * 16 + q]);
        a2.x = fmaf(zv, w.x, a2.x);
        a2.y = fmaf(zv, w.y, a2.y);
        a2.z = fmaf(zv, w.z, a2.z);
        a2.w = fmaf(zv, w.w, a2.w);
    }
    if (valid)
        *reinterpret_cast<float4*>(d_h2 + (size_t)node * 64 + (q << 2)) = a2;
}

// per node: v = relu(gather(h2) + h2[i]*dinv^2 + b2), block-reduced sum into d_sums
__global__ void k_gather2(const float* __restrict__ b2, const int* __restrict__ batch, int n) {
    int node = (blockIdx.x * 256 + threadIdx.x) >> 4;
    int q = threadIdx.x & 15;
    bool valid = node < n;
    int nd = valid ? node : (n - 1);
    float di = d_dinv[nd];
    int s0 = d_start[nd];
    int e1 = s0 + (valid ? d_ideg[nd] : 0);
    float4 acc = make_float4(0.f, 0.f, 0.f, 0.f);
#pragma unroll 4
    for (int e = s0; e < e1; e++) {
        int s = __ldg(&d_esrc[e]);
        float nr = __ldg(&d_dinv[s]) * di;
        float4 v = *reinterpret_cast<const float4*>(d_h2 + (size_t)s * 64 + (q << 2));
        acc.x = fmaf(v.x, nr, acc.x); acc.y = fmaf(v.y, nr, acc.y);
        acc.z = fmaf(v.z, nr, acc.z); acc.w = fmaf(v.w, nr, acc.w);
    }
    int g = batch[nd];
    float4 v = make_float4(0.f, 0.f, 0.f, 0.f);
    if (valid) {
        float dd = di * di;
        float4 hv = *reinterpret_cast<const float4*>(d_h2 + (size_t)nd * 64 + (q << 2));
        float4 bb = *reinterpret_cast<const float4*>(b2 + (q << 2));
        v.x = fmaxf(acc.x + hv.x * dd + bb.x, 0.f);
        v.y = fmaxf(acc.y + hv.y * dd + bb.y, 0.f);
        v.z = fmaxf(acc.z + hv.z * dd + bb.z, 0.f);
        v.w = fmaxf(acc.w + hv.w * dd + bb.w, 0.f);
    }
    __shared__ float4 sv[256];
    __shared__ int sg[16];
    int grp = threadIdx.x >> 4;
    if (q == 0) sg[grp] = g;
    sv[threadIdx.x] = v;
    __syncthreads();
    int uni = __syncthreads_and(g == sg[0]);
    if (uni) {
#pragma unroll
        for (int st = 8; st >= 1; st >>= 1) {
            if (grp < st) {
                float4 o = sv[threadIdx.x + (st << 4)];
                sv[threadIdx.x].x += o.x; sv[threadIdx.x].y += o.y;
                sv[threadIdx.x].z += o.z; sv[threadIdx.x].w += o.w;
            }
            __syncthreads();
        }
        if (grp == 0) {
            float4 r = sv[q];
            float* p = d_sums + sg[0] * 64 + (q << 2);
            asm volatile("red.global.add.v4.f32 [%0], {%1,%2,%3,%4};"
                         :: "l"(p), "f"(r.x), "f"(r.y), "f"(r.z), "f"(r.w) : "memory");
        }
    } else {
        float* p = d_sums + g * 64 + (q << 2);
        asm volatile("red.global.add.v4.f32 [%0], {%1,%2,%3,%4};"
                     :: "l"(p), "f"(v.x), "f"(v.y), "f"(v.z), "f"(v.w) : "memory");
    }
}

// out[g][0:64] = sums/max(cnt,1);  out[g][64:128] = h1[root_g] (0 if empty)
__global__ void k_out(float* __restrict__ out) {
    int g = blockIdx.x;
    int j = threadIdx.x;
    float c = (float)d_cnt[g];
    float val;
    if (j < 64) val = d_sums[g * 64 + j] / fmaxf(c, 1.0f);
    else        val = (c > 0.0f) ? d_rooth1[g * 64 + (j - 64)] : 0.0f;
    out[g * 128 + j] = val;
}

// ---------------- launcher (single stream, no allocations) ----------------
extern "C" void kernel_launch(void* const* d_in, const int* in_sizes, int n_in,
                              void* d_out, int out_size) {
    const float* x     = (const float*)d_in[0];
    const int*   ei    = (const int*)d_in[1];    // int32 (JAX x64 disabled)
    const int*   batch = (const int*)d_in[2];
    const float* W1    = (const float*)d_in[3];
    const float* b1    = (const float*)d_in[4];
    const float* W2    = (const float*)d_in[5];
    const float* b2    = (const float*)d_in[6];
    float*       out   = (float*)d_out;

    int n = in_sizes[0] / 128;   // 100000
    int e = in_sizes[1] / 2;     // 3200000
    int g = out_size / 128;      // 128

    const int* src = ei;
    const int* dst = ei + e;

    int nb_n    = (n + 255) / 256;
    int nb_e    = (e + 255) / 256;
    int nb_scan = (n + 1023) / 1024;
    int nb_gth  = (n * 16 + 255) / 256;

    k_init    <<<nb_n, 256>>>(n, g);
    k_hist    <<<nb_e, 256>>>(dst, e);
    k_scan1   <<<nb_scan, 256>>>(n);
    k_scan2   <<<1, 128>>>(nb_scan);
    k_scan3   <<<nb_n, 256>>>(n);
    // fused: CSR placement | x@W1 | root scan — independent work, one launch
    k_setup   <<<nb_e + nb_gth + nb_n, 256>>>(src, dst, x, W1, batch, e, n, nb_e, nb_gth);
    k_rc      <<<g, 64>>>(x, W2);
    k_gather1 <<<nb_gth, 256>>>(b1, batch, W2, n);
    k_gather2 <<<nb_gth, 256>>>(b2, batch, n);
    k_out     <<<g, 128>>>(out);
}

// round 9
// speedup vs baseline: 2.1392x; 1.0901x over previous
#include <cuda_runtime.h>
#include <cuda_fp16.h>

#define NN  100000
#define EE  3200000
#define GMAX 128

// ---------------- scratch (no allocations allowed) ----------------
__device__ __align__(16) __half d_h [NN * 64];   // x @ W1       (fp16 messages)
__device__ __align__(16) __half d_h2[NN * 64];   // layer-2 pre-aggregation (fp16)
__device__ float d_dinv[NN];
__device__ int   d_ideg [NN];     // in-degree (edges by dst)
__device__ int   d_start[NN];     // CSR row starts (by dst)
__device__ int   d_cur  [NN];     // placement cursors
__device__ int   d_esrc [EE];     // src ids sorted by dst
__device__ int   d_bsum [256];
__device__ int   d_root [GMAX];
__device__ __align__(16) float d_rc    [GMAX * 64]; // relu(x[root]) @ W2[64:192]
__device__ __align__(16) float d_rooth1[GMAX * 64]; // h1 at roots (fp32!)
__device__ __align__(16) float d_sums  [GMAX * 64];
__device__ int   d_cnt [GMAX];

// half helpers ---------------------------------------------------------
__device__ __forceinline__ void store_h4(__half* base, float4 v) {
    union { __half2 h2[2]; uint2 u; } pk;
    pk.h2[0] = __floats2half2_rn(v.x, v.y);
    pk.h2[1] = __floats2half2_rn(v.z, v.w);
    *reinterpret_cast<uint2*>(base) = pk.u;
}
__device__ __forceinline__ float4 load_h4(const __half* base) {
    uint2 raw = __ldg(reinterpret_cast<const uint2*>(base));
    __half2 a = *reinterpret_cast<__half2*>(&raw.x);
    __half2 b = *reinterpret_cast<__half2*>(&raw.y);
    float2 f0 = __half22float2(a), f1 = __half22float2(b);
    return make_float4(f0.x, f0.y, f1.x, f1.y);
}

// ---------------- setup ----------------

__global__ void k_init(int n, int g) {
    int i = blockIdx.x * blockDim.x + threadIdx.x;
    if (i < n) d_ideg[i] = 0;
    if (i < g * 64) d_sums[i] = 0.0f;
    if (i < g) { d_cnt[i] = 0; d_root[i] = n - 1; }
}

// fused: hist (atomic pipe) | gemm1 (FMA pipe) | root scan
// blocks [0,nbE): hist    [nbE,nbE+nbG): h = x@W1 (fp16 out)    [+nbN): root
__global__ void k_work1(const int* __restrict__ dst,
                        const float* __restrict__ x, const float* __restrict__ W1,
                        const int* __restrict__ batch,
                        int e, int n, int nbE, int nbG) {
    int role_b = blockIdx.x;
    if (role_b < nbE) {
        int i = role_b * 256 + threadIdx.x;
        if (i < e) atomicAdd(&d_ideg[dst[i]], 1);
        return;
    }
    role_b -= nbE;
    if (role_b < nbG) {
        int node = (role_b * 256 + threadIdx.x) >> 4;
        int q  = threadIdx.x & 15;
        int nl = threadIdx.x >> 4;
        __shared__ float4 xs[16][32];
        bool valid = node < n;
        int nd = valid ? node : (n - 1);
        const float4* xr = reinterpret_cast<const float4*>(x + (size_t)nd * 128);
        xs[nl][q]      = xr[q];
        xs[nl][16 + q] = xr[16 + q];
        __syncwarp();
        const float4* W = reinterpret_cast<const float4*>(W1);
        const float* xf = reinterpret_cast<const float*>(xs[nl]);
        float4 acc = make_float4(0.f, 0.f, 0.f, 0.f);
#pragma unroll 8
        for (int k = 0; k < 128; k++) {
            float xv = xf[k];
            float4 w = __ldg(&W[k * 16 + q]);
            acc.x = fmaf(xv, w.x, acc.x);
            acc.y = fmaf(xv, w.y, acc.y);
            acc.z = fmaf(xv, w.z, acc.z);
            acc.w = fmaf(xv, w.w, acc.w);
        }
        if (valid) store_h4(d_h + (size_t)node * 64 + (q << 2), acc);
        return;
    }
    role_b -= nbG;
    int i = role_b * 256 + threadIdx.x;
    if (i < n) {
        int g = batch[i];
        atomicMin(&d_root[g], i);
        atomicAdd(&d_cnt[g], 1);
    }
}

// block scan: 1024 elems / block (256 thr x 4); within-block exclusive + block sums
__global__ void k_scan1(int n) {
    __shared__ int sm[256];
    int t = threadIdx.x, b = blockIdx.x;
    int base = b * 1024 + t * 4;
    int v[4]; int s = 0;
#pragma unroll
    for (int u = 0; u < 4; u++) {
        int i = base + u;
        v[u] = (i < n) ? d_ideg[i] : 0;
        s += v[u];
    }
    sm[t] = s; __syncthreads();
#pragma unroll
    for (int off = 1; off < 256; off <<= 1) {
        int x = (t >= off) ? sm[t - off] : 0;
        __syncthreads();
        sm[t] += x;
        __syncthreads();
    }
    int excl = sm[t] - s;
#pragma unroll
    for (int u = 0; u < 4; u++) {
        int i = base + u;
        if (i < n) d_start[i] = excl;
        excl += v[u];
    }
    if (t == 255) d_bsum[b] = sm[255];
}

// fused scan2+scan3: each block re-scans the (<=128) block sums in smem,
// then applies its offset; also seeds cursors and dinv.
__global__ void k_scan23(int n, int nb) {
    __shared__ int sm[128];
    __shared__ int boff;
    int t = threadIdx.x, b = blockIdx.x;
    if (t < 128) sm[t] = (t < nb) ? d_bsum[t] : 0;
    __syncthreads();
#pragma unroll
    for (int off = 1; off < 128; off <<= 1) {
        int x = (t < 128 && t >= off) ? sm[t - off] : 0;
        __syncthreads();
        if (t < 128) sm[t] += x;
        __syncthreads();
    }
    if (t == 0) boff = (b == 0) ? 0 : sm[b - 1];
    __syncthreads();
    int base = b * 1024 + t * 4;
#pragma unroll
    for (int u = 0; u < 4; u++) {
        int i = base + u;
        if (i < n) {
            int st = d_start[i] + boff;
            d_start[i] = st;
            d_cur[i] = st;
            d_dinv[i] = rsqrtf((float)d_ideg[i] + 1.0f);
        }
    }
}

// fused: CSR placement | rc
// blocks [0,nbE): place     [nbE, nbE+ceil(g/4)): rc, 4 graphs per block
__global__ void k_work2(const int* __restrict__ src, const int* __restrict__ dst,
                        const float* __restrict__ x, const float* __restrict__ W2,
                        int e, int g, int nbE) {
    int role_b = blockIdx.x;
    if (role_b < nbE) {
        int i = role_b * 256 + threadIdx.x;
        if (i < e) {
            int d = dst[i];
            int pos = atomicAdd(&d_cur[d], 1);
            d_esrc[pos] = src[i];
        }
        return;
    }
    role_b -= nbE;
    int gi = role_b * 4 + (threadIdx.x >> 6);
    int j  = threadIdx.x & 63;
    __shared__ float xs[4][128];
    if (gi >= g) return;
    int grp = threadIdx.x >> 6;
    int r = d_root[gi];
    xs[grp][j]      = fmaxf(x[(size_t)r * 128 + j], 0.0f);
    xs[grp][64 + j] = fmaxf(x[(size_t)r * 128 + 64 + j], 0.0f);
    __syncwarp();  // 64-thread group spans 2 warps...
    __syncthreads();
    float acc = 0.0f;
#pragma unroll 8
    for (int k = 0; k < 128; k++)
        acc = fmaf(xs[grp][k], __ldg(&W2[(64 + k) * 64 + j]), acc);
    d_rc[gi * 64 + j] = acc;
}

// ---------------- fused gather1 + gemm2 ----------------
// h1 = gather(h) + h*dinv^2 + b1        (h1 stored fp32 only for roots)
// h2 = relu(h1) @ W2[0:64] + rc[batch]  (fp16 out)
__global__ void k_gather1(const float* __restrict__ b1, const int* __restrict__ batch,
                          const float* __restrict__ W2, int n) {
    int node = (blockIdx.x * 256 + threadIdx.x) >> 4;
    int q  = threadIdx.x & 15;
    int nl = threadIdx.x >> 4;
    __shared__ float4 zs[16][16];
    bool valid = node < n;
    int nd = valid ? node : (n - 1);
    float di = d_dinv[nd];
    int s0 = d_start[nd];
    int e1 = s0 + (valid ? d_ideg[nd] : 0);
    float4 acc = make_float4(0.f, 0.f, 0.f, 0.f);
#pragma unroll 4
    for (int e = s0; e < e1; e++) {
        int s = __ldg(&d_esrc[e]);
        float nr = __ldg(&d_dinv[s]) * di;
        float4 v = load_h4(d_h + (size_t)s * 64 + (q << 2));
        acc.x = fmaf(v.x, nr, acc.x); acc.y = fmaf(v.y, nr, acc.y);
        acc.z = fmaf(v.z, nr, acc.z); acc.w = fmaf(v.w, nr, acc.w);
    }
    float dd = di * di;
    float4 hv = load_h4(d_h + (size_t)nd * 64 + (q << 2));
    float4 bb = *reinterpret_cast<const float4*>(b1 + (q << 2));
    float4 r;
    r.x = acc.x + hv.x * dd + bb.x;
    r.y = acc.y + hv.y * dd + bb.y;
    r.z = acc.z + hv.z * dd + bb.z;
    r.w = acc.w + hv.w * dd + bb.w;

    int g = batch[nd];
    if (valid && d_root[g] == node)
        *reinterpret_cast<float4*>(d_rooth1 + g * 64 + (q << 2)) = r;

    float4 z;
    z.x = fmaxf(r.x, 0.f); z.y = fmaxf(r.y, 0.f);
    z.z = fmaxf(r.z, 0.f); z.w = fmaxf(r.w, 0.f);
    zs[nl][q] = z;
    __syncwarp();

    const float4* W = reinterpret_cast<const float4*>(W2);
    float4 a2 = *reinterpret_cast<const float4*>(d_rc + g * 64 + (q << 2));
    const float* zf = reinterpret_cast<const float*>(zs[nl]);
#pragma unroll 8
    for (int k = 0; k < 64; k++) {
        float zv = zf[k];
        float4 w = __ldg(&W[k * 16 + q]);
        a2.x = fmaf(zv, w.x, a2.x);
        a2.y = fmaf(zv, w.y, a2.y);
        a2.z = fmaf(zv, w.z, a2.z);
        a2.w = fmaf(zv, w.w, a2.w);
    }
    if (valid) store_h4(d_h2 + (size_t)node * 64 + (q << 2), a2);
}

// per node: v = relu(gather(h2) + h2[i]*dinv^2 + b2), block-reduced into d_sums
__global__ void k_gather2(const float* __restrict__ b2, const int* __restrict__ batch, int n) {
    int node = (blockIdx.x * 256 + threadIdx.x) >> 4;
    int q = threadIdx.x & 15;
    bool valid = node < n;
    int nd = valid ? node : (n - 1);
    float di = d_dinv[nd];
    int s0 = d_start[nd];
    int e1 = s0 + (valid ? d_ideg[nd] : 0);
    float4 acc = make_float4(0.f, 0.f, 0.f, 0.f);
#pragma unroll 4
    for (int e = s0; e < e1; e++) {
        int s = __ldg(&d_esrc[e]);
        float nr = __ldg(&d_dinv[s]) * di;
        float4 v = load_h4(d_h2 + (size_t)s * 64 + (q << 2));
        acc.x = fmaf(v.x, nr, acc.x); acc.y = fmaf(v.y, nr, acc.y);
        acc.z = fmaf(v.z, nr, acc.z); acc.w = fmaf(v.w, nr, acc.w);
    }
    int g = batch[nd];
    float4 v = make_float4(0.f, 0.f, 0.f, 0.f);
    if (valid) {
        float dd = di * di;
        float4 hv = load_h4(d_h2 + (size_t)nd * 64 + (q << 2));
        float4 bb = *reinterpret_cast<const float4*>(b2 + (q << 2));
        v.x = fmaxf(acc.x + hv.x * dd + bb.x, 0.f);
        v.y = fmaxf(acc.y + hv.y * dd + bb.y, 0.f);
        v.z = fmaxf(acc.z + hv.z * dd + bb.z, 0.f);
        v.w = fmaxf(acc.w + hv.w * dd + bb.w, 0.f);
    }
    __shared__ float4 sv[256];
    __shared__ int sg[16];
    int grp = threadIdx.x >> 4;
    if (q == 0) sg[grp] = g;
    sv[threadIdx.x] = v;
    __syncthreads();
    int uni = __syncthreads_and(g == sg[0]);
    if (uni) {
#pragma unroll
        for (int st = 8; st >= 1; st >>= 1) {
            if (grp < st) {
                float4 o = sv[threadIdx.x + (st << 4)];
                sv[threadIdx.x].x += o.x; sv[threadIdx.x].y += o.y;
                sv[threadIdx.x].z += o.z; sv[threadIdx.x].w += o.w;
            }
            __syncthreads();
        }
        if (grp == 0) {
            float4 r = sv[q];
            float* p = d_sums + sg[0] * 64 + (q << 2);
            asm volatile("red.global.add.v4.f32 [%0], {%1,%2,%3,%4};"
                         :: "l"(p), "f"(r.x), "f"(r.y), "f"(r.z), "f"(r.w) : "memory");
        }
    } else {
        float* p = d_sums + g * 64 + (q << 2);
        asm volatile("red.global.add.v4.f32 [%0], {%1,%2,%3,%4};"
                     :: "l"(p), "f"(v.x), "f"(v.y), "f"(v.z), "f"(v.w) : "memory");
    }
}

// out[g][0:64] = sums/max(cnt,1);  out[g][64:128] = h1[root_g] (0 if empty)
__global__ void k_out(float* __restrict__ out) {
    int g = blockIdx.x;
    int j = threadIdx.x;
    float c = (float)d_cnt[g];
    float val;
    if (j < 64) val = d_sums[g * 64 + j] / fmaxf(c, 1.0f);
    else        val = (c > 0.0f) ? d_rooth1[g * 64 + (j - 64)] : 0.0f;
    out[g * 128 + j] = val;
}

// ---------------- launcher (single stream, no allocations) ----------------
extern "C" void kernel_launch(void* const* d_in, const int* in_sizes, int n_in,
                              void* d_out, int out_size) {
    const float* x     = (const float*)d_in[0];
    const int*   ei    = (const int*)d_in[1];    // int32 (JAX x64 disabled)
    const int*   batch = (const int*)d_in[2];
    const float* W1    = (const float*)d_in[3];
    const float* b1    = (const float*)d_in[4];
    const float* W2    = (const float*)d_in[5];
    const float* b2    = (const float*)d_in[6];
    float*       out   = (float*)d_out;

    int n = in_sizes[0] / 128;   // 100000
    int e = in_sizes[1] / 2;     // 3200000
    int g = out_size / 128;      // 128

    const int* src = ei;
    const int* dst = ei + e;

    int nb_n    = (n + 255) / 256;
    int nb_e    = (e + 255) / 256;
    int nb_scan = (n + 1023) / 1024;
    int nb_gth  = (n * 16 + 255) / 256;
    int nb_rc   = (g + 3) / 4;

    k_init    <<<nb_n, 256>>>(n, g);
    k_work1   <<<nb_e + nb_gth + nb_n, 256>>>(dst, x, W1, batch, e, n, nb_e, nb_gth);
    k_scan1   <<<nb_scan, 256>>>(n);
    k_scan23  <<<nb_scan, 256>>>(n, nb_scan);
    k_work2   <<<nb_e + nb_rc, 256>>>(src, dst, x, W2, e, g, nb_e);
    k_gather1 <<<nb_gth, 256>>>(b1, batch, W2, n);
    k_gather2 <<<nb_gth, 256>>>(b2, batch, n);
    k_out     <<<g, 128>>>(out);
}

// round 10
// speedup vs baseline: 2.2397x; 1.0470x over previous
#include <cuda_runtime.h>
#include <cuda_fp16.h>

#define NN  100000
#define EE  3200000
#define GMAX 128

// ---------------- scratch (no allocations allowed) ----------------
// d_h : x@W1, later scaled in-place by dinv[node] (fp16)
// d_h2: (relu(h1)@W2 + rc) * dinv[node]  (fp16, pre-scaled at creation)
__device__ __align__(16) __half d_h [NN * 64];
__device__ __align__(16) __half d_h2[NN * 64];
__device__ float d_dinv[NN];
__device__ int   d_ideg [NN];
__device__ int   d_start[NN];
__device__ int   d_cur  [NN];
__device__ int   d_esrc [EE];
__device__ int   d_bsum [256];
__device__ int   d_root [GMAX];
__device__ __align__(16) float d_rc    [GMAX * 64];
__device__ __align__(16) float d_rooth1[GMAX * 64];
__device__ __align__(16) float d_sums  [GMAX * 64];
__device__ int   d_cnt [GMAX];

// half helpers ---------------------------------------------------------
__device__ __forceinline__ void store_h4(__half* base, float4 v) {
    union { __half2 h2[2]; uint2 u; } pk;
    pk.h2[0] = __floats2half2_rn(v.x, v.y);
    pk.h2[1] = __floats2half2_rn(v.z, v.w);
    *reinterpret_cast<uint2*>(base) = pk.u;
}
__device__ __forceinline__ float4 load_h4(const __half* base) {
    uint2 raw = __ldg(reinterpret_cast<const uint2*>(base));
    __half2 a = *reinterpret_cast<__half2*>(&raw.x);
    __half2 b = *reinterpret_cast<__half2*>(&raw.y);
    float2 f0 = __half22float2(a), f1 = __half22float2(b);
    return make_float4(f0.x, f0.y, f1.x, f1.y);
}

// ---------------- setup ----------------

__global__ void k_init(int n, int g) {
    int i = blockIdx.x * blockDim.x + threadIdx.x;
    if (i < n) d_ideg[i] = 0;
    if (i < g * 64) d_sums[i] = 0.0f;
    if (i < g) { d_cnt[i] = 0; d_root[i] = n - 1; }
}

// fused: hist | gemm1 (fp16 out, unscaled) | root scan
__global__ void k_work1(const int* __restrict__ dst,
                        const float* __restrict__ x, const float* __restrict__ W1,
                        const int* __restrict__ batch,
                        int e, int n, int nbE, int nbG) {
    int role_b = blockIdx.x;
    if (role_b < nbE) {
        int i = role_b * 256 + threadIdx.x;
        if (i < e) atomicAdd(&d_ideg[dst[i]], 1);
        return;
    }
    role_b -= nbE;
    if (role_b < nbG) {
        int node = (role_b * 256 + threadIdx.x) >> 4;
        int q  = threadIdx.x & 15;
        int nl = threadIdx.x >> 4;
        __shared__ float4 xs[16][32];
        bool valid = node < n;
        int nd = valid ? node : (n - 1);
        const float4* xr = reinterpret_cast<const float4*>(x + (size_t)nd * 128);
        xs[nl][q]      = xr[q];
        xs[nl][16 + q] = xr[16 + q];
        __syncwarp();
        const float4* W = reinterpret_cast<const float4*>(W1);
        float4 acc = make_float4(0.f, 0.f, 0.f, 0.f);
#pragma unroll 8
        for (int k4 = 0; k4 < 32; k4++) {
            float4 xv = xs[nl][k4];
            float4 w0 = __ldg(&W[(k4 * 4 + 0) * 16 + q]);
            float4 w1 = __ldg(&W[(k4 * 4 + 1) * 16 + q]);
            float4 w2 = __ldg(&W[(k4 * 4 + 2) * 16 + q]);
            float4 w3 = __ldg(&W[(k4 * 4 + 3) * 16 + q]);
            acc.x = fmaf(xv.x, w0.x, acc.x); acc.y = fmaf(xv.x, w0.y, acc.y);
            acc.z = fmaf(xv.x, w0.z, acc.z); acc.w = fmaf(xv.x, w0.w, acc.w);
            acc.x = fmaf(xv.y, w1.x, acc.x); acc.y = fmaf(xv.y, w1.y, acc.y);
            acc.z = fmaf(xv.y, w1.z, acc.z); acc.w = fmaf(xv.y, w1.w, acc.w);
            acc.x = fmaf(xv.z, w2.x, acc.x); acc.y = fmaf(xv.z, w2.y, acc.y);
            acc.z = fmaf(xv.z, w2.z, acc.z); acc.w = fmaf(xv.z, w2.w, acc.w);
            acc.x = fmaf(xv.w, w3.x, acc.x); acc.y = fmaf(xv.w, w3.y, acc.y);
            acc.z = fmaf(xv.w, w3.z, acc.z); acc.w = fmaf(xv.w, w3.w, acc.w);
        }
        if (valid) store_h4(d_h + (size_t)node * 64 + (q << 2), acc);
        return;
    }
    role_b -= nbG;
    int i = role_b * 256 + threadIdx.x;
    if (i < n) {
        int g = batch[i];
        atomicMin(&d_root[g], i);
        atomicAdd(&d_cnt[g], 1);
    }
}

// block scan: 1024 elems / block
__global__ void k_scan1(int n) {
    __shared__ int sm[256];
    int t = threadIdx.x, b = blockIdx.x;
    int base = b * 1024 + t * 4;
    int v[4]; int s = 0;
#pragma unroll
    for (int u = 0; u < 4; u++) {
        int i = base + u;
        v[u] = (i < n) ? d_ideg[i] : 0;
        s += v[u];
    }
    sm[t] = s; __syncthreads();
#pragma unroll
    for (int off = 1; off < 256; off <<= 1) {
        int x = (t >= off) ? sm[t - off] : 0;
        __syncthreads();
        sm[t] += x;
        __syncthreads();
    }
    int excl = sm[t] - s;
#pragma unroll
    for (int u = 0; u < 4; u++) {
        int i = base + u;
        if (i < n) d_start[i] = excl;
        excl += v[u];
    }
    if (t == 255) d_bsum[b] = sm[255];
}

// fused scan2+scan3
__global__ void k_scan23(int n, int nb) {
    __shared__ int sm[128];
    __shared__ int boff;
    int t = threadIdx.x, b = blockIdx.x;
    if (t < 128) sm[t] = (t < nb) ? d_bsum[t] : 0;
    __syncthreads();
#pragma unroll
    for (int off = 1; off < 128; off <<= 1) {
        int x = (t < 128 && t >= off) ? sm[t - off] : 0;
        __syncthreads();
        if (t < 128) sm[t] += x;
        __syncthreads();
    }
    if (t == 0) boff = (b == 0) ? 0 : sm[b - 1];
    __syncthreads();
    int base = b * 1024 + t * 4;
#pragma unroll
    for (int u = 0; u < 4; u++) {
        int i = base + u;
        if (i < n) {
            int st = d_start[i] + boff;
            d_start[i] = st;
            d_cur[i] = st;
            d_dinv[i] = rsqrtf((float)d_ideg[i] + 1.0f);
        }
    }
}

// fused: place | scale d_h by dinv | rc
// blocks [0,nbE): place   [nbE,nbE+nbS): h *= dinv[node]   [+nbRC): rc
__global__ void k_work2(const int* __restrict__ src, const int* __restrict__ dst,
                        const float* __restrict__ x, const float* __restrict__ W2,
                        int e, int n, int g, int nbE, int nbS) {
    int role_b = blockIdx.x;
    if (role_b < nbE) {
        int i = role_b * 256 + threadIdx.x;
        if (i < e) {
            int d = dst[i];
            int pos = atomicAdd(&d_cur[d], 1);
            d_esrc[pos] = src[i];
        }
        return;
    }
    role_b -= nbE;
    if (role_b < nbS) {
        int i = role_b * 256 + threadIdx.x;   // i over n*16 quads
        if (i < n * 16) {
            int node = i >> 4;
            float di = d_dinv[node];
            __half* p = d_h + ((size_t)i << 2);
            float4 v = load_h4(p);
            v.x *= di; v.y *= di; v.z *= di; v.w *= di;
            store_h4(p, v);
        }
        return;
    }
    role_b -= nbS;
    int gi = role_b * 4 + (threadIdx.x >> 6);
    int j  = threadIdx.x & 63;
    __shared__ float xs[4][128];
    if (gi >= g) return;
    int grp = threadIdx.x >> 6;
    int r = d_root[gi];
    xs[grp][j]      = fmaxf(x[(size_t)r * 128 + j], 0.0f);
    xs[grp][64 + j] = fmaxf(x[(size_t)r * 128 + 64 + j], 0.0f);
    __syncthreads();
    float acc = 0.0f;
#pragma unroll 8
    for (int k = 0; k < 128; k++)
        acc = fmaf(xs[grp][k], __ldg(&W2[(64 + k) * 64 + j]), acc);
    d_rc[gi * 64 + j] = acc;
}

// ---------------- fused gather1 + gemm2 ----------------
// acc = sum of pre-scaled rows; h1 = (acc + h_s[nd]) * dinv[nd] + b1
// h2_scaled = (relu(h1) @ W2[0:64] + rc[g]) * dinv[nd]   (fp16 out)
__global__ void k_gather1(const float* __restrict__ b1, const int* __restrict__ batch,
                          const float* __restrict__ W2, int n) {
    int node = (blockIdx.x * 256 + threadIdx.x) >> 4;
    int q  = threadIdx.x & 15;
    int nl = threadIdx.x >> 4;
    __shared__ float4 zs[16][16];
    bool valid = node < n;
    int nd = valid ? node : (n - 1);
    float di = d_dinv[nd];
    int s0 = d_start[nd];
    int e1 = s0 + (valid ? d_ideg[nd] : 0);
    float4 acc = make_float4(0.f, 0.f, 0.f, 0.f);
#pragma unroll 4
    for (int e = s0; e < e1; e++) {
        int s = __ldg(&d_esrc[e]);
        float4 v = load_h4(d_h + (size_t)s * 64 + (q << 2));
        acc.x += v.x; acc.y += v.y; acc.z += v.z; acc.w += v.w;
    }
    float4 hv = load_h4(d_h + (size_t)nd * 64 + (q << 2));
    float4 bb = *reinterpret_cast<const float4*>(b1 + (q << 2));
    float4 r;
    r.x = fmaf(acc.x + hv.x, di, bb.x);
    r.y = fmaf(acc.y + hv.y, di, bb.y);
    r.z = fmaf(acc.z + hv.z, di, bb.z);
    r.w = fmaf(acc.w + hv.w, di, bb.w);

    int g = batch[nd];
    if (valid && d_root[g] == node)
        *reinterpret_cast<float4*>(d_rooth1 + g * 64 + (q << 2)) = r;

    float4 z;
    z.x = fmaxf(r.x, 0.f); z.y = fmaxf(r.y, 0.f);
    z.z = fmaxf(r.z, 0.f); z.w = fmaxf(r.w, 0.f);
    zs[nl][q] = z;
    __syncwarp();

    const float4* W = reinterpret_cast<const float4*>(W2);
    float4 a2 = *reinterpret_cast<const float4*>(d_rc + g * 64 + (q << 2));
#pragma unroll 4
    for (int k4 = 0; k4 < 16; k4++) {
        float4 zv = zs[nl][k4];
        float4 w0 = __ldg(&W[(k4 * 4 + 0) * 16 + q]);
        float4 w1 = __ldg(&W[(k4 * 4 + 1) * 16 + q]);
        float4 w2 = __ldg(&W[(k4 * 4 + 2) * 16 + q]);
        float4 w3 = __ldg(&W[(k4 * 4 + 3) * 16 + q]);
        a2.x = fmaf(zv.x, w0.x, a2.x); a2.y = fmaf(zv.x, w0.y, a2.y);
        a2.z = fmaf(zv.x, w0.z, a2.z); a2.w = fmaf(zv.x, w0.w, a2.w);
        a2.x = fmaf(zv.y, w1.x, a2.x); a2.y = fmaf(zv.y, w1.y, a2.y);
        a2.z = fmaf(zv.y, w1.z, a2.z); a2.w = fmaf(zv.y, w1.w, a2.w);
        a2.x = fmaf(zv.z, w2.x, a2.x); a2.y = fmaf(zv.z, w2.y, a2.y);
        a2.z = fmaf(zv.z, w2.z, a2.z); a2.w = fmaf(zv.z, w2.w, a2.w);
        a2.x = fmaf(zv.w, w3.x, a2.x); a2.y = fmaf(zv.w, w3.y, a2.y);
        a2.z = fmaf(zv.w, w3.z, a2.z); a2.w = fmaf(zv.w, w3.w, a2.w);
    }
    if (valid) {
        a2.x *= di; a2.y *= di; a2.z *= di; a2.w *= di;  // pre-scale for gather2
        store_h4(d_h2 + (size_t)node * 64 + (q << 2), a2);
    }
}

// v = relu((sum of pre-scaled h2 rows + h2_s[nd]) * dinv + b2); block-reduce into sums
__global__ void k_gather2(const float* __restrict__ b2, const int* __restrict__ batch, int n) {
    int node = (blockIdx.x * 256 + threadIdx.x) >> 4;
    int q = threadIdx.x & 15;
    bool valid = node < n;
    int nd = valid ? node : (n - 1);
    float di = d_dinv[nd];
    int s0 = d_start[nd];
    int e1 = s0 + (valid ? d_ideg[nd] : 0);
    float4 acc = make_float4(0.f, 0.f, 0.f, 0.f);
#pragma unroll 4
    for (int e = s0; e < e1; e++) {
        int s = __ldg(&d_esrc[e]);
        float4 v = load_h4(d_h2 + (size_t)s * 64 + (q << 2));
        acc.x += v.x; acc.y += v.y; acc.z += v.z; acc.w += v.w;
    }
    int g = batch[nd];
    float4 v = make_float4(0.f, 0.f, 0.f, 0.f);
    if (valid) {
        float4 hv = load_h4(d_h2 + (size_t)nd * 64 + (q << 2));
        float4 bb = *reinterpret_cast<const float4*>(b2 + (q << 2));
        v.x = fmaxf(fmaf(acc.x + hv.x, di, bb.x), 0.f);
        v.y = fmaxf(fmaf(acc.y + hv.y, di, bb.y), 0.f);
        v.z = fmaxf(fmaf(acc.z + hv.z, di, bb.z), 0.f);
        v.w = fmaxf(fmaf(acc.w + hv.w, di, bb.w), 0.f);
    }
    __shared__ float4 sv[256];
    __shared__ int sg[16];
    int grp = threadIdx.x >> 4;
    if (q == 0) sg[grp] = g;
    sv[threadIdx.x] = v;
    __syncthreads();
    int uni = __syncthreads_and(g == sg[0]);
    if (uni) {
#pragma unroll
        for (int st = 8; st >= 1; st >>= 1) {
            if (grp < st) {
                float4 o = sv[threadIdx.x + (st << 4)];
                sv[threadIdx.x].x += o.x; sv[threadIdx.x].y += o.y;
                sv[threadIdx.x].z += o.z; sv[threadIdx.x].w += o.w;
            }
            __syncthreads();
        }
        if (grp == 0) {
            float4 r = sv[q];
            float* p = d_sums + sg[0] * 64 + (q << 2);
            asm volatile("red.global.add.v4.f32 [%0], {%1,%2,%3,%4};"
                         :: "l"(p), "f"(r.x), "f"(r.y), "f"(r.z), "f"(r.w) : "memory");
        }
    } else {
        float* p = d_sums + g * 64 + (q << 2);
        asm volatile("red.global.add.v4.f32 [%0], {%1,%2,%3,%4};"
                     :: "l"(p), "f"(v.x), "f"(v.y), "f"(v.z), "f"(v.w) : "memory");
    }
}

__global__ void k_out(float* __restrict__ out) {
    int g = blockIdx.x;
    int j = threadIdx.x;
    float c = (float)d_cnt[g];
    float val;
    if (j < 64) val = d_sums[g * 64 + j] / fmaxf(c, 1.0f);
    else        val = (c > 0.0f) ? d_rooth1[g * 64 + (j - 64)] : 0.0f;
    out[g * 128 + j] = val;
}

// ---------------- launcher (single stream, no allocations) ----------------
extern "C" void kernel_launch(void* const* d_in, const int* in_sizes, int n_in,
                              void* d_out, int out_size) {
    const float* x     = (const float*)d_in[0];
    const int*   ei    = (const int*)d_in[1];    // int32 (JAX x64 disabled)
    const int*   batch = (const int*)d_in[2];
    const float* W1    = (const float*)d_in[3];
    const float* b1    = (const float*)d_in[4];
    const float* W2    = (const float*)d_in[5];
    const float* b2    = (const float*)d_in[6];
    float*       out   = (float*)d_out;

    int n = in_sizes[0] / 128;   // 100000
    int e = in_sizes[1] / 2;     // 3200000
    int g = out_size / 128;      // 128

    const int* src = ei;
    const int* dst = ei + e;

    int nb_n    = (n + 255) / 256;
    int nb_e    = (e + 255) / 256;
    int nb_scan = (n + 1023) / 1024;
    int nb_gth  = (n * 16 + 255) / 256;
    int nb_rc   = (g + 3) / 4;

    k_init    <<<nb_n, 256>>>(n, g);
    k_work1   <<<nb_e + nb_gth + nb_n, 256>>>(dst, x, W1, batch, e, n, nb_e, nb_gth);
    k_scan1   <<<nb_scan, 256>>>(n);
    k_scan23  <<<nb_scan, 256>>>(n, nb_scan);
    k_work2   <<<nb_e + nb_gth + nb_rc, 256>>>(src, dst, x, W2, e, n, g, nb_e, nb_gth);
    k_gather1 <<<nb_gth, 256>>>(b1, batch, W2, n);
    k_gather2 <<<nb_gth, 256>>>(b2, batch, n);
    k_out     <<<g, 128>>>(out);
}